// round 1
// baseline (speedup 1.0000x reference)
#include <cuda_runtime.h>

// Problem constants (fixed by the reference)
#define BSZ   2
#define LEN   2048
#define DQ    512
#define SQ    4
#define NC    64                 // number of chunks along L
#define CHUNK (LEN / NC)         // 32 steps per chunk
#define EPSQ  1e-6f

// Scratch: chunk summaries and carries, laid out [b][chunk][s][d] (d contiguous
// so K1/K3 accesses coalesce across the warp's d-lanes).
__device__ float4 g_Q  [BSZ * NC * SQ * DQ];
__device__ float4 g_H  [BSZ * NC * SQ * DQ];
__device__ float4 g_Hin[BSZ * NC * SQ * DQ];

// ---------------------------------------------------------------------------
// Quaternion helpers (FMA-friendly; negations fold into FFMA modifiers)
// ---------------------------------------------------------------------------
__device__ __forceinline__ float4 qmuladd(const float4 a, const float4 b, const float4 c) {
    float4 r;
    r.x = fmaf(a.x, b.x, fmaf(-a.y, b.y, fmaf(-a.z, b.z, fmaf(-a.w, b.w, c.x))));
    r.y = fmaf(a.x, b.y, fmaf( a.y, b.x, fmaf( a.z, b.w, fmaf(-a.w, b.z, c.y))));
    r.z = fmaf(a.x, b.z, fmaf(-a.y, b.w, fmaf( a.z, b.x, fmaf( a.w, b.y, c.z))));
    r.w = fmaf(a.x, b.w, fmaf( a.y, b.z, fmaf(-a.z, b.y, fmaf( a.w, b.x, c.w))));
    return r;
}
__device__ __forceinline__ float4 qmul(const float4 a, const float4 b) {
    return qmuladd(a, b, make_float4(0.f, 0.f, 0.f, 0.f));
}

// Fast accurate reciprocal: MUFU.RCP + one Newton step (error ~2^-44 pre-round)
__device__ __forceinline__ float frcp_fast(float x) {
    float r;
    asm("rcp.approx.f32 %0, %1;" : "=f"(r) : "f"(x));
    return r * (2.0f - x * r);
}

// Per-step transition/injection math.
// Given dtv (scalar), half-scaled A quaternion ah = 0.5*A, B quaternion, u quaternion:
//   w   = dtv * ah
//   q   = (1 - |w|^2, 2*w_v) * rinv,  rinv = 1/((1-w_r)^2 + |w_v|^2 + eps)
//   g   = (1-w_r, w_v) * (dtv * rinv)           [= den_inv * dt]
//   Bu  = (g (x) B) (x) u
__device__ __forceinline__ void step_qbu(const float dtv, const float4 ah,
                                         const float4 Bq, const float4 uu,
                                         float4& q, float4& Bu) {
    const float wr = dtv * ah.x, wi = dtv * ah.y, wj = dtv * ah.z, wk = dtv * ah.w;
    const float omr = 1.0f - wr;
    const float vv  = fmaf(wi, wi, fmaf(wj, wj, wk * wk));
    const float n2  = fmaf(omr, omr, vv) + EPSQ;
    const float m2  = fmaf(wr, wr, vv);
    const float rinv = frcp_fast(n2);
    q = make_float4((1.0f - m2) * rinv, 2.0f * wi * rinv, 2.0f * wj * rinv, 2.0f * wk * rinv);
    const float e = dtv * rinv;
    const float4 g = make_float4(omr * e, wi * e, wj * e, wk * e);
    const float4 dB = qmul(g, Bq);
    Bu = qmul(dB, uu);
}

__device__ __forceinline__ void load_ah(const float* __restrict__ A_log,
                                        const float* __restrict__ A_i,
                                        const float* __restrict__ A_j,
                                        const float* __restrict__ A_k,
                                        int d, float4 ah[SQ]) {
#pragma unroll
    for (int s = 0; s < SQ; s++) {
        const int ai = d * SQ + s;
        ah[s] = make_float4(-0.5f * expf(A_log[ai]), 0.5f * A_i[ai],
                             0.5f * A_j[ai],          0.5f * A_k[ai]);
    }
}

// ---------------------------------------------------------------------------
// K1: per-(b, chunk, d) thread — compute chunk transforms (Q_total, H_total)
//     for all 4 s lanes. h starts at 0 inside the chunk.
// ---------------------------------------------------------------------------
__global__ void __launch_bounds__(256)
k_summary(const float* __restrict__ u, const float* __restrict__ dt,
          const float* __restrict__ Bin,
          const float* __restrict__ A_log, const float* __restrict__ A_i,
          const float* __restrict__ A_j,  const float* __restrict__ A_k)
{
    const int tid = blockIdx.x * blockDim.x + threadIdx.x;
    const int d = tid % DQ;
    const int c = (tid / DQ) % NC;
    const int b = tid / (DQ * NC);
    if (b >= BSZ) return;

    float4 ah[SQ];
    load_ah(A_log, A_i, A_j, A_k, d, ah);

    float4 Q[SQ], H[SQ];
#pragma unroll
    for (int s = 0; s < SQ; s++) {
        Q[s] = make_float4(1.f, 0.f, 0.f, 0.f);
        H[s] = make_float4(0.f, 0.f, 0.f, 0.f);
    }

    const float4* __restrict__ u4 = (const float4*)u;
    const float4* __restrict__ B4 = (const float4*)Bin;

    const int t0 = c * CHUNK;
    for (int i = 0; i < CHUNK; i++) {
        const int t  = t0 + i;
        const int td = b * LEN + t;
        const float  dtv = dt[td * DQ + d];
        const float4 uu  = u4[td * DQ + d];
#pragma unroll
        for (int s = 0; s < SQ; s++) {
            const float4 Bq = B4[td * SQ + s];
            float4 q, Bu;
            step_qbu(dtv, ah[s], Bq, uu, q, Bu);
            H[s] = qmuladd(q, H[s], Bu);
            Q[s] = qmul(q, Q[s]);
        }
    }

#pragma unroll
    for (int s = 0; s < SQ; s++) {
        const int idx = ((b * NC + c) * SQ + s) * DQ + d;
        g_Q[idx] = Q[s];
        g_H[idx] = H[s];
    }
}

// ---------------------------------------------------------------------------
// K2: per-(b, s, d) thread — sequential scan over the NC chunk transforms,
//     producing the carry-in state for each chunk. Tiny kernel (4096 threads).
// ---------------------------------------------------------------------------
__global__ void __launch_bounds__(256)
k_carry()
{
    const int tid = blockIdx.x * blockDim.x + threadIdx.x;
    const int d = tid % DQ;
    const int s = (tid / DQ) % SQ;
    const int b = tid / (DQ * SQ);
    if (b >= BSZ) return;

    float4 carry = make_float4(0.f, 0.f, 0.f, 0.f);
    for (int c = 0; c < NC; c++) {
        const int idx = ((b * NC + c) * SQ + s) * DQ + d;
        g_Hin[idx] = carry;
        carry = qmuladd(g_Q[idx], carry, g_H[idx]);
    }
}

// ---------------------------------------------------------------------------
// K3: per-(b, chunk, d) thread — recompute the chunk with carry-in known,
//     accumulate y over all 4 s lanes in-thread, write float4 output.
// ---------------------------------------------------------------------------
__global__ void __launch_bounds__(256)
k_final(const float* __restrict__ u, const float* __restrict__ dt,
        const float* __restrict__ Bin, const float* __restrict__ Cin,
        const float* __restrict__ A_log, const float* __restrict__ A_i,
        const float* __restrict__ A_j,  const float* __restrict__ A_k,
        float* __restrict__ out)
{
    const int tid = blockIdx.x * blockDim.x + threadIdx.x;
    const int d = tid % DQ;
    const int c = (tid / DQ) % NC;
    const int b = tid / (DQ * NC);
    if (b >= BSZ) return;

    float4 ah[SQ];
    load_ah(A_log, A_i, A_j, A_k, d, ah);

    float4 h[SQ];
#pragma unroll
    for (int s = 0; s < SQ; s++)
        h[s] = g_Hin[((b * NC + c) * SQ + s) * DQ + d];

    const float4* __restrict__ u4 = (const float4*)u;
    const float4* __restrict__ B4 = (const float4*)Bin;
    const float4* __restrict__ C4 = (const float4*)Cin;
    float4* __restrict__ o4 = (float4*)out;

    const int t0 = c * CHUNK;
    for (int i = 0; i < CHUNK; i++) {
        const int t  = t0 + i;
        const int td = b * LEN + t;
        const float  dtv = dt[td * DQ + d];
        const float4 uu  = u4[td * DQ + d];
        float4 y = make_float4(0.f, 0.f, 0.f, 0.f);
#pragma unroll
        for (int s = 0; s < SQ; s++) {
            const float4 Bq = B4[td * SQ + s];
            const float4 Cq = C4[td * SQ + s];
            float4 q, Bu;
            step_qbu(dtv, ah[s], Bq, uu, q, Bu);
            h[s] = qmuladd(q, h[s], Bu);
            y = qmuladd(Cq, h[s], y);
        }
        o4[td * DQ + d] = y;
    }
}

// ---------------------------------------------------------------------------
// Launch: three graph-capturable kernel launches, no allocs, no syncs.
// Inputs (metadata order): u, dt, B_in, C_in, A_log, A_i, A_j, A_k
// ---------------------------------------------------------------------------
extern "C" void kernel_launch(void* const* d_in, const int* in_sizes, int n_in,
                              void* d_out, int out_size)
{
    const float* u     = (const float*)d_in[0];
    const float* dt    = (const float*)d_in[1];
    const float* Bin   = (const float*)d_in[2];
    const float* Cin   = (const float*)d_in[3];
    const float* A_log = (const float*)d_in[4];
    const float* A_i   = (const float*)d_in[5];
    const float* A_j   = (const float*)d_in[6];
    const float* A_k   = (const float*)d_in[7];
    float* out = (float*)d_out;

    const int heavy_threads = BSZ * NC * DQ;   // 65536
    const int carry_threads = BSZ * SQ * DQ;   // 4096

    k_summary<<<heavy_threads / 256, 256>>>(u, dt, Bin, A_log, A_i, A_j, A_k);
    k_carry<<<(carry_threads + 255) / 256, 256>>>();
    k_final<<<heavy_threads / 256, 256>>>(u, dt, Bin, Cin, A_log, A_i, A_j, A_k, out);
}